// round 15
// baseline (speedup 1.0000x reference)
#include <cuda_runtime.h>

namespace {
constexpr int T_STEPS = 256;
constexpr int B_SZ    = 4096;
constexpr int HID     = 64;
constexpr int MLPW    = 128;
constexpr int DOUT    = 8;
constexpr int RP      = 2;            // row-pairs per warp => 4 rows/warp
constexpr int NWARPS  = 14;           // 7 drift/diff warp-pairs per CTA
constexpr int QP      = NWARPS / 2;   // warp-pairs per CTA
constexpr int NSTEP   = 255;
constexpr int NCTA    = 148;          // 148 * 7 * 4 = 4144 >= 4096; tail pairs idle
}

using ull = unsigned long long;

struct QShm {                     // one drift/diff warp-pair's staging (8 KB)
    ull   aIn[RP][HID];           // zhat input, row-paired         (1 KB)
    ull   hD [RP][MLPW];          // drift MLP scratch + readout    (2 KB)
    ull   hF [RP][MLPW];          // diff MLP scratch               (2 KB)
    ull   gEx[RP][HID];           // g exchange                     (1 KB)
    float dwRaw[2][2 * RP][HID];  // RAW dW double buffer (cp.async)(2 KB)
};

__device__ __forceinline__ ull fma2(ull a, ull b, ull c) {
    ull d; asm("fma.rn.f32x2 %0, %1, %2, %3;" : "=l"(d) : "l"(a), "l"(b), "l"(c)); return d;
}
__device__ __forceinline__ ull add2(ull a, ull b) {
    ull d; asm("add.rn.f32x2 %0, %1, %2;" : "=l"(d) : "l"(a), "l"(b)); return d;
}
__device__ __forceinline__ ull mul2(ull a, ull b) {
    ull d; asm("mul.rn.f32x2 %0, %1, %2;" : "=l"(d) : "l"(a), "l"(b)); return d;
}
__device__ __forceinline__ ull splat2(float x) {
    ull d; unsigned u = __float_as_uint(x);
    asm("mov.b64 %0, {%1, %1};" : "=l"(d) : "r"(u)); return d;
}
__device__ __forceinline__ ull pack2(float lo, float hi) {
    ull d; unsigned a = __float_as_uint(lo), b = __float_as_uint(hi);
    asm("mov.b64 %0, {%1, %2};" : "=l"(d) : "r"(a), "r"(b)); return d;
}
__device__ __forceinline__ float2 unpack2(ull v) {
    float2 r; asm("mov.b64 {%0, %1}, %2;" : "=f"(r.x), "=f"(r.y) : "l"(v)); return r;
}
__device__ __forceinline__ float4 ldg4(const float* p){ return __ldg((const float4*)p); }
__device__ __forceinline__ float2 ldg2f(const float* p){ return __ldg((const float2*)p); }
__device__ __forceinline__ float lipswish(float x){
    float s = 1.0f / (1.0f + __expf(-x)); return 0.909f * x * s;
}
__device__ __forceinline__ void pair_sync(int q) {
    asm volatile("bar.sync %0, 64;" :: "r"(q + 1) : "memory");
}
__device__ __forceinline__ unsigned smem_u32(const void* p) {
    unsigned a;
    asm("{ .reg .u64 t; cvta.to.shared.u64 t, %1; cvt.u32.u64 %0, t; }"
        : "=r"(a) : "l"(p));
    return a;
}
#define CP_ASYNC16(dst, src) \
    asm volatile("cp.async.cg.shared.global [%0], [%1], 16;" :: "r"(dst), "l"(src) : "memory")
#define CP_COMMIT() asm volatile("cp.async.commit_group;" ::: "memory")
#define CP_WAIT0()  asm volatile("cp.async.wait_group 0;"  ::: "memory")

// acc[p][c]: (row2p, row2p+1) for lane cols 4l..4l+3. aS row-paired, stride K.
template<int K>
__device__ __forceinline__ void gemm128_rp(const float* __restrict__ W,
                                           const ull* __restrict__ aS,
                                           ull acc[RP][4], int lane)
{
    const float* Wp = W + 4 * lane;
#pragma unroll 4
    for (int kb = 0; kb < K / 4; kb++) {
        ulonglong2 a0[RP], a1[RP];
#pragma unroll
        for (int p = 0; p < RP; p++) {
            a0[p] = *reinterpret_cast<const ulonglong2*>(aS + p * K + kb * 4);
            a1[p] = *reinterpret_cast<const ulonglong2*>(aS + p * K + kb * 4 + 2);
        }
        float4 wv[4];
#pragma unroll
        for (int kk = 0; kk < 4; kk++)
            wv[kk] = ldg4(Wp + (kb * 4 + kk) * MLPW);
#pragma unroll
        for (int kk = 0; kk < 4; kk++) {
            ull w0 = splat2(wv[kk].x), w1 = splat2(wv[kk].y);
            ull w2 = splat2(wv[kk].z), w3 = splat2(wv[kk].w);
#pragma unroll
            for (int p = 0; p < RP; p++) {
                ull av = (kk == 0) ? a0[p].x : (kk == 1) ? a0[p].y
                       : (kk == 2) ? a1[p].x : a1[p].y;
                acc[p][0] = fma2(av, w0, acc[p][0]);
                acc[p][1] = fma2(av, w1, acc[p][1]);
                acc[p][2] = fma2(av, w2, acc[p][2]);
                acc[p][3] = fma2(av, w3, acc[p][3]);
            }
        }
    }
}

// N=64 output layer: lane cols 2l..2l+1, acc[p][j].
template<int K>
__device__ __forceinline__ void gemm64_rp(const float* __restrict__ W,
                                          const ull* __restrict__ aS,
                                          ull acc[RP][2], int lane)
{
    const float* Wp = W + 2 * lane;
#pragma unroll 4
    for (int kb = 0; kb < K / 4; kb++) {
        ulonglong2 a0[RP], a1[RP];
#pragma unroll
        for (int p = 0; p < RP; p++) {
            a0[p] = *reinterpret_cast<const ulonglong2*>(aS + p * K + kb * 4);
            a1[p] = *reinterpret_cast<const ulonglong2*>(aS + p * K + kb * 4 + 2);
        }
        float2 wv[4];
#pragma unroll
        for (int kk = 0; kk < 4; kk++)
            wv[kk] = ldg2f(Wp + (kb * 4 + kk) * HID);
#pragma unroll
        for (int kk = 0; kk < 4; kk++) {
            ull w0 = splat2(wv[kk].x), w1 = splat2(wv[kk].y);
#pragma unroll
            for (int p = 0; p < RP; p++) {
                ull av = (kk == 0) ? a0[p].x : (kk == 1) ? a0[p].y
                       : (kk == 2) ? a1[p].x : a1[p].y;
                acc[p][0] = fma2(av, w0, acc[p][0]);
                acc[p][1] = fma2(av, w1, acc[p][1]);
            }
        }
    }
}

__device__ __forceinline__ void mlp_rp(
    float tn,
    const float* __restrict__ W0, const float* __restrict__ b0,
    const float* __restrict__ W1, const float* __restrict__ b1,
    const float* __restrict__ Wo, const float* __restrict__ bo,
    const ull* __restrict__ aIn, ull* __restrict__ hS,
    ull out[RP][2], int lane)
{
    ull acc[RP][4];
    {   // bias + t * W0_row0 (same for both packed rows -> splat)
        float4 bv = ldg4(b0 + 4 * lane);
        float4 w0 = ldg4(W0 + 4 * lane);
        ull i0 = splat2(fmaf(tn, w0.x, bv.x));
        ull i1 = splat2(fmaf(tn, w0.y, bv.y));
        ull i2 = splat2(fmaf(tn, w0.z, bv.z));
        ull i3 = splat2(fmaf(tn, w0.w, bv.w));
#pragma unroll
        for (int p = 0; p < RP; p++) {
            acc[p][0] = i0; acc[p][1] = i1; acc[p][2] = i2; acc[p][3] = i3;
        }
    }
    gemm128_rp<HID>(W0 + MLPW, aIn, acc, lane);   // rows 1..64 of W0
#pragma unroll
    for (int p = 0; p < RP; p++) {
        ulonglong2 s0, s1;
        { float2 v = unpack2(acc[p][0]); s0.x = pack2(lipswish(v.x), lipswish(v.y)); }
        { float2 v = unpack2(acc[p][1]); s0.y = pack2(lipswish(v.x), lipswish(v.y)); }
        { float2 v = unpack2(acc[p][2]); s1.x = pack2(lipswish(v.x), lipswish(v.y)); }
        { float2 v = unpack2(acc[p][3]); s1.y = pack2(lipswish(v.x), lipswish(v.y)); }
        *reinterpret_cast<ulonglong2*>(hS + p * MLPW + 4 * lane)     = s0;
        *reinterpret_cast<ulonglong2*>(hS + p * MLPW + 4 * lane + 2) = s1;
    }
    __syncwarp();

    {
        float4 bv = ldg4(b1 + 4 * lane);
        ull i0 = splat2(bv.x), i1 = splat2(bv.y), i2 = splat2(bv.z), i3 = splat2(bv.w);
#pragma unroll
        for (int p = 0; p < RP; p++) {
            acc[p][0] = i0; acc[p][1] = i1; acc[p][2] = i2; acc[p][3] = i3;
        }
    }
    gemm128_rp<MLPW>(W1, hS, acc, lane);
    __syncwarp();   // all lanes done reading h1 before in-place overwrite
#pragma unroll
    for (int p = 0; p < RP; p++) {
        ulonglong2 s0, s1;
        { float2 v = unpack2(acc[p][0]); s0.x = pack2(lipswish(v.x), lipswish(v.y)); }
        { float2 v = unpack2(acc[p][1]); s0.y = pack2(lipswish(v.x), lipswish(v.y)); }
        { float2 v = unpack2(acc[p][2]); s1.x = pack2(lipswish(v.x), lipswish(v.y)); }
        { float2 v = unpack2(acc[p][3]); s1.y = pack2(lipswish(v.x), lipswish(v.y)); }
        *reinterpret_cast<ulonglong2*>(hS + p * MLPW + 4 * lane)     = s0;
        *reinterpret_cast<ulonglong2*>(hS + p * MLPW + 4 * lane + 2) = s1;
    }
    __syncwarp();

    ull acc2[RP][2];
    {
        float2 bv = ldg2f(bo + 2 * lane);
        ull i0 = splat2(bv.x), i1 = splat2(bv.y);
#pragma unroll
        for (int p = 0; p < RP; p++) { acc2[p][0] = i0; acc2[p][1] = i1; }
    }
    gemm64_rp<MLPW>(Wo, hS, acc2, lane);
#pragma unroll
    for (int p = 0; p < RP; p++) {
#pragma unroll
        for (int j = 0; j < 2; j++) {
            float2 v = unpack2(acc2[p][j]);
            out[p][j] = pack2(tanhf(v.x), tanhf(v.y));
        }
    }
}

// Drift warp only. Unpacks row-paired z into compact zc (reuses hD), then
// lane (r = lane>>3, d = lane&7) computes readout for 4 rows.
__device__ __forceinline__ void readout_rp(
    const ull z[RP][2], float* __restrict__ zc,
    const float (*sRWt)[68], const float* __restrict__ sRB,
    float* __restrict__ out, int rowbase, int tIdx, float tval, int lane)
{
#pragma unroll
    for (int p = 0; p < RP; p++) {
        float2 v0 = unpack2(z[p][0]);     // (row2p_c0, row2p+1_c0)
        float2 v1 = unpack2(z[p][1]);
        *reinterpret_cast<float2*>(zc + (2 * p) * HID + 2 * lane)     = make_float2(v0.x, v1.x);
        *reinterpret_cast<float2*>(zc + (2 * p + 1) * HID + 2 * lane) = make_float2(v0.y, v1.y);
    }
    __syncwarp();
    const int d = lane & 7;
    const int r = lane >> 3;
    float acc = sRB[d];
#pragma unroll
    for (int hb = 0; hb < HID / 4; hb++) {
        float4 zv = *reinterpret_cast<const float4*>(zc + r * HID + hb * 4);
        float4 wv = *reinterpret_cast<const float4*>(&sRWt[d][hb * 4]);
        acc = fmaf(zv.x, wv.x, acc);
        acc = fmaf(zv.y, wv.y, acc);
        acc = fmaf(zv.z, wv.z, acc);
        acc = fmaf(zv.w, wv.w, acc);
    }
    size_t base = ((size_t)(rowbase + r) * T_STEPS + tIdx) * (DOUT + 1);
    out[base + 1 + d] = acc;
    if (d == 0) out[base] = tval;
    __syncwarp();   // zc (hD) reads done before the MLP overwrites it
}

__global__ void __launch_bounds__(NWARPS * 32, 1)
sde_kernel(const float* __restrict__ ts,
           const float* __restrict__ dW,
           const float* __restrict__ dW0, const float* __restrict__ db0,
           const float* __restrict__ dW1, const float* __restrict__ db1,
           const float* __restrict__ dWo, const float* __restrict__ dbo,
           const float* __restrict__ fW0, const float* __restrict__ fb0,
           const float* __restrict__ fW1, const float* __restrict__ fb1,
           const float* __restrict__ fWo, const float* __restrict__ fbo,
           const float* __restrict__ RW, const float* __restrict__ rb,
           float* __restrict__ out)
{
    extern __shared__ char dyn[];
    QShm* Q = reinterpret_cast<QShm*>(dyn);
    float (*sRWt)[68] = reinterpret_cast<float(*)[68]>(dyn + QP * sizeof(QShm));
    float* sRB = reinterpret_cast<float*>(dyn + QP * sizeof(QShm) + DOUT * 68 * sizeof(float));

    const int tid  = threadIdx.x;
    const int w    = tid >> 5;
    const int lane = tid & 31;
    const int q    = w >> 1;
    const bool isDrift = (w & 1) == 0;
    QShm& S = Q[q];
    ull* hS = isDrift ? &S.hD[0][0] : &S.hF[0][0];
    const int rowbase = (blockIdx.x * QP + q) * (2 * RP);

    for (int i = tid; i < HID * DOUT; i += blockDim.x)
        sRWt[i & 7][i >> 3] = __ldg(RW + i);        // RW is (64, 8) row-major
    if (tid < DOUT) sRB[tid] = __ldg(rb + tid);

    const float t0  = __ldg(ts + 0);
    const float dt  = __ldg(ts + 1) - t0;
    const float sdt = sqrtf(dt);
    const ull dt2   = splat2(dt);
    const ull hdt2  = splat2(0.5f * dt);
    const ull half2 = splat2(0.5f);
    const ull two2  = splat2(2.0f);
    const ull one2  = splat2(1.0f);
    const ull sdt2  = splat2(sdt);
    constexpr ull SGN2 = 0x8000000080000000ULL;

    const float* W0 = isDrift ? dW0 : fW0; const float* b0 = isDrift ? db0 : fb0;
    const float* W1 = isDrift ? dW1 : fW1; const float* b1 = isDrift ? db1 : fb1;
    const float* Wo = isDrift ? dWo : fWo; const float* bo = isDrift ? dbo : fbo;

    ull z[RP][2], zh[RP][2], fq[RP][2], g[RP][2], res[RP][2];

    __syncthreads();   // sRWt visible block-wide (before any early exit)

    if (rowbase >= B_SZ) return;   // tail pairs (48 of 4144 row-slots) idle

    const unsigned dwRawAddr = smem_u32(&S.dwRaw[0][0][0]);   // 2 x 1024 B

    if (isDrift) {
#pragma unroll
        for (int p = 0; p < RP; p++) {
            z[p][0] = z[p][1] = one2;
            zh[p][0] = zh[p][1] = one2;
            ulonglong2 o; o.x = one2; o.y = one2;
            *reinterpret_cast<ulonglong2*>(&S.aIn[p][2 * lane]) = o;
        }
    } else {
        // cp.async raw dW rows (t=0) into buffer 0: 4 rows x 256 B, contiguous
        const char* gsrc = (const char*)(dW + (size_t)rowbase * HID);
        CP_ASYNC16(dwRawAddr + lane * 16u,        gsrc + lane * 16);
        CP_ASYNC16(dwRawAddr + lane * 16u + 512u, gsrc + lane * 16 + 512);
        CP_COMMIT();
    }
    pair_sync(q);      // initial aIn staging visible within the pair

    // f0 / g0 at t = ts[0], x0 = ones
    mlp_rp(t0, W0, b0, W1, b1, Wo, bo, &S.aIn[0][0], hS, res, lane);
    if (!isDrift) {
#pragma unroll
        for (int p = 0; p < RP; p++) {
            ulonglong2 v; v.x = res[p][0]; v.y = res[p][1];
            *reinterpret_cast<ulonglong2*>(&S.gEx[p][2 * lane]) = v;
        }
        CP_WAIT0();    // buffer 0 landed (hidden under the mlp above)
    }
    pair_sync(q);

    if (isDrift) {
#pragma unroll
        for (int p = 0; p < RP; p++) {
            fq[p][0] = res[p][0]; fq[p][1] = res[p][1];
            ulonglong2 v = *reinterpret_cast<const ulonglong2*>(&S.gEx[p][2 * lane]);
            g[p][0] = v.x; g[p][1] = v.y;
        }
    }

    float tprev = t0;
    for (int n = 0; n < NSTEP; n++) {
        const float tn = __ldg(ts + n + 1);

        if (isDrift) {
            // load raw dW, transform to row-paired * sqrt(dt) in regs
            const float* raw = &S.dwRaw[n & 1][0][0];
#pragma unroll
            for (int p = 0; p < RP; p++) {
                float2 a = *reinterpret_cast<const float2*>(raw + (2 * p) * HID + 2 * lane);
                float2 b = *reinterpret_cast<const float2*>(raw + (2 * p + 1) * HID + 2 * lane);
                ull dwp0 = mul2(pack2(a.x, b.x), sdt2);
                ull dwp1 = mul2(pack2(a.y, b.y), sdt2);
                // zhat_{n+1} = 2z - zhat + f dt + g dw
                ull t1;
                t1 = fma2(two2, z[p][0], zh[p][0] ^ SGN2);
                t1 = fma2(fq[p][0], dt2, t1);
                zh[p][0] = fma2(g[p][0], dwp0, t1);
                t1 = fma2(two2, z[p][1], zh[p][1] ^ SGN2);
                t1 = fma2(fq[p][1], dt2, t1);
                zh[p][1] = fma2(g[p][1], dwp1, t1);
                ulonglong2 o; o.x = zh[p][0]; o.y = zh[p][1];
                *reinterpret_cast<ulonglong2*>(&S.aIn[p][2 * lane]) = o;
            }
        }
        pair_sync(q);      // B1: aIn ready

        if (!isDrift) {
            // fire-and-forget next step's raw dW (hidden under the gemms)
            const int m = (n + 1 < NSTEP) ? (n + 1) : (NSTEP - 1);
            const char* gsrc = (const char*)(dW + ((size_t)m * B_SZ + rowbase) * HID);
            unsigned dst = dwRawAddr + (((n + 1) & 1) ? 1024u : 0u) + lane * 16u;
            CP_ASYNC16(dst,        gsrc + lane * 16);
            CP_ASYNC16(dst + 512u, gsrc + lane * 16 + 512);
            CP_COMMIT();
        } else {
            // readout of z_n (overlaps the diff warp's gemm)
            readout_rp(z, reinterpret_cast<float*>(&S.hD[0][0]), sRWt, sRB,
                       out, rowbase, n, tprev, lane);
        }

        mlp_rp(tn, W0, b0, W1, b1, Wo, bo, &S.aIn[0][0], hS, res, lane);

        if (!isDrift) {
#pragma unroll
            for (int p = 0; p < RP; p++) {
                ulonglong2 v; v.x = res[p][0]; v.y = res[p][1];
                *reinterpret_cast<ulonglong2*>(&S.gEx[p][2 * lane]) = v;
            }
            CP_WAIT0();    // next-step dW landed
        }
        pair_sync(q);      // B2: gEx + next dwRaw ready

        if (isDrift) {
            const float* raw = &S.dwRaw[n & 1][0][0];
#pragma unroll
            for (int p = 0; p < RP; p++) {
                float2 a = *reinterpret_cast<const float2*>(raw + (2 * p) * HID + 2 * lane);
                float2 b = *reinterpret_cast<const float2*>(raw + (2 * p + 1) * HID + 2 * lane);
                ull dwp[2];
                dwp[0] = mul2(pack2(a.x, b.x), sdt2);
                dwp[1] = mul2(pack2(a.y, b.y), sdt2);
                ulonglong2 gv = *reinterpret_cast<const ulonglong2*>(&S.gEx[p][2 * lane]);
                ull gn[2] = { gv.x, gv.y };
#pragma unroll
                for (int j = 0; j < 2; j++) {
                    ull s1 = add2(fq[p][j], res[p][j]);
                    z[p][j] = fma2(s1, hdt2, z[p][j]);
                    ull s2 = mul2(add2(g[p][j], gn[j]), half2);
                    z[p][j] = fma2(s2, dwp[j], z[p][j]);
                    fq[p][j] = res[p][j];
                    g[p][j]  = gn[j];
                }
            }
        }
        tprev = tn;
    }

    // drain the final state: z_255 at tIdx 255
    if (isDrift) {
        readout_rp(z, reinterpret_cast<float*>(&S.hD[0][0]), sRWt, sRB,
                   out, rowbase, NSTEP, tprev, lane);
    }
}

extern "C" void kernel_launch(void* const* d_in, const int* in_sizes, int n_in,
                              void* d_out, int out_size) {
    (void)in_sizes; (void)n_in; (void)out_size;
    const float* ts  = (const float*)d_in[0];
    // d_in[1] = batch_size (int32 scalar) — shapes are fixed constants here
    const float* dW  = (const float*)d_in[2];
    const float* dW0 = (const float*)d_in[3];
    const float* db0 = (const float*)d_in[4];
    const float* dW1 = (const float*)d_in[5];
    const float* db1 = (const float*)d_in[6];
    const float* dWo = (const float*)d_in[7];
    const float* dbo = (const float*)d_in[8];
    const float* fW0 = (const float*)d_in[9];
    const float* fb0 = (const float*)d_in[10];
    const float* fW1 = (const float*)d_in[11];
    const float* fb1 = (const float*)d_in[12];
    const float* fWo = (const float*)d_in[13];
    const float* fbo = (const float*)d_in[14];
    const float* RW  = (const float*)d_in[15];
    const float* rb  = (const float*)d_in[16];
    float* out = (float*)d_out;

    const int smem = QP * (int)sizeof(QShm) + DOUT * 68 * (int)sizeof(float) + 64;
    cudaFuncSetAttribute(sde_kernel, cudaFuncAttributeMaxDynamicSharedMemorySize, smem);

    sde_kernel<<<NCTA, NWARPS * 32, smem>>>(ts, dW,
                                            dW0, db0, dW1, db1, dWo, dbo,
                                            fW0, fb0, fW1, fb1, fWo, fbo,
                                            RW, rb, out);
}

// round 16
// speedup vs baseline: 1.0051x; 1.0051x over previous
#include <cuda_runtime.h>

namespace {
constexpr int T_STEPS = 256;
constexpr int B_SZ    = 4096;
constexpr int HID     = 64;
constexpr int MLPW    = 128;
constexpr int DOUT    = 8;
constexpr int RP      = 2;            // row-pairs per warp => 4 rows/warp
constexpr int NWARPS  = 14;           // 7 drift/diff warp-pairs per CTA
constexpr int QP      = NWARPS / 2;   // warp-pairs per CTA
constexpr int NSTEP   = 255;
constexpr int NCTA    = 148;          // 148 * 7 * 4 = 4144 >= 4096; tail pairs idle
}

using ull = unsigned long long;

struct QShm {                     // one drift/diff warp-pair's staging (11 KB)
    ull   aIn[2][RP][HID];        // per-role zhat input, row-paired (2 KB)
    ull   hD [RP][MLPW];          // drift MLP scratch + readout     (2 KB)
    ull   hF [RP][MLPW];          // diff MLP scratch                (2 KB)
    ull   ex [2][RP][HID];        // f (role 0) / g (role 1) exchange(2 KB)
    float dwRaw[3][2 * RP][HID];  // RAW dW 3-slot ring (cp.async)   (3 KB)
};

__device__ __forceinline__ ull fma2(ull a, ull b, ull c) {
    ull d; asm("fma.rn.f32x2 %0, %1, %2, %3;" : "=l"(d) : "l"(a), "l"(b), "l"(c)); return d;
}
__device__ __forceinline__ ull add2(ull a, ull b) {
    ull d; asm("add.rn.f32x2 %0, %1, %2;" : "=l"(d) : "l"(a), "l"(b)); return d;
}
__device__ __forceinline__ ull mul2(ull a, ull b) {
    ull d; asm("mul.rn.f32x2 %0, %1, %2;" : "=l"(d) : "l"(a), "l"(b)); return d;
}
__device__ __forceinline__ ull splat2(float x) {
    ull d; unsigned u = __float_as_uint(x);
    asm("mov.b64 %0, {%1, %1};" : "=l"(d) : "r"(u)); return d;
}
__device__ __forceinline__ ull pack2(float lo, float hi) {
    ull d; unsigned a = __float_as_uint(lo), b = __float_as_uint(hi);
    asm("mov.b64 %0, {%1, %2};" : "=l"(d) : "r"(a), "r"(b)); return d;
}
__device__ __forceinline__ float2 unpack2(ull v) {
    float2 r; asm("mov.b64 {%0, %1}, %2;" : "=f"(r.x), "=f"(r.y) : "l"(v)); return r;
}
__device__ __forceinline__ float4 ldg4(const float* p){ return __ldg((const float4*)p); }
__device__ __forceinline__ float2 ldg2f(const float* p){ return __ldg((const float2*)p); }
__device__ __forceinline__ float lipswish(float x){
    float s = 1.0f / (1.0f + __expf(-x)); return 0.909f * x * s;
}
__device__ __forceinline__ void pair_sync(int q) {
    asm volatile("bar.sync %0, 64;" :: "r"(q + 1) : "memory");
}
__device__ __forceinline__ unsigned smem_u32(const void* p) {
    unsigned a;
    asm("{ .reg .u64 t; cvta.to.shared.u64 t, %1; cvt.u32.u64 %0, t; }"
        : "=r"(a) : "l"(p));
    return a;
}
#define CP_ASYNC16(dst, src) \
    asm volatile("cp.async.cg.shared.global [%0], [%1], 16;" :: "r"(dst), "l"(src) : "memory")
#define CP_COMMIT() asm volatile("cp.async.commit_group;" ::: "memory")
#define CP_WAIT0()  asm volatile("cp.async.wait_group 0;"  ::: "memory")

// acc[p][c]: (row2p, row2p+1) for lane cols 4l..4l+3. aS row-paired, stride K.
template<int K>
__device__ __forceinline__ void gemm128_rp(const float* __restrict__ W,
                                           const ull* __restrict__ aS,
                                           ull acc[RP][4], int lane)
{
    const float* Wp = W + 4 * lane;
#pragma unroll 4
    for (int kb = 0; kb < K / 4; kb++) {
        ulonglong2 a0[RP], a1[RP];
#pragma unroll
        for (int p = 0; p < RP; p++) {
            a0[p] = *reinterpret_cast<const ulonglong2*>(aS + p * K + kb * 4);
            a1[p] = *reinterpret_cast<const ulonglong2*>(aS + p * K + kb * 4 + 2);
        }
        float4 wv[4];
#pragma unroll
        for (int kk = 0; kk < 4; kk++)
            wv[kk] = ldg4(Wp + (kb * 4 + kk) * MLPW);
#pragma unroll
        for (int kk = 0; kk < 4; kk++) {
            ull w0 = splat2(wv[kk].x), w1 = splat2(wv[kk].y);
            ull w2 = splat2(wv[kk].z), w3 = splat2(wv[kk].w);
#pragma unroll
            for (int p = 0; p < RP; p++) {
                ull av = (kk == 0) ? a0[p].x : (kk == 1) ? a0[p].y
                       : (kk == 2) ? a1[p].x : a1[p].y;
                acc[p][0] = fma2(av, w0, acc[p][0]);
                acc[p][1] = fma2(av, w1, acc[p][1]);
                acc[p][2] = fma2(av, w2, acc[p][2]);
                acc[p][3] = fma2(av, w3, acc[p][3]);
            }
        }
    }
}

// N=64 output layer: lane cols 2l..2l+1, acc[p][j].
template<int K>
__device__ __forceinline__ void gemm64_rp(const float* __restrict__ W,
                                          const ull* __restrict__ aS,
                                          ull acc[RP][2], int lane)
{
    const float* Wp = W + 2 * lane;
#pragma unroll 4
    for (int kb = 0; kb < K / 4; kb++) {
        ulonglong2 a0[RP], a1[RP];
#pragma unroll
        for (int p = 0; p < RP; p++) {
            a0[p] = *reinterpret_cast<const ulonglong2*>(aS + p * K + kb * 4);
            a1[p] = *reinterpret_cast<const ulonglong2*>(aS + p * K + kb * 4 + 2);
        }
        float2 wv[4];
#pragma unroll
        for (int kk = 0; kk < 4; kk++)
            wv[kk] = ldg2f(Wp + (kb * 4 + kk) * HID);
#pragma unroll
        for (int kk = 0; kk < 4; kk++) {
            ull w0 = splat2(wv[kk].x), w1 = splat2(wv[kk].y);
#pragma unroll
            for (int p = 0; p < RP; p++) {
                ull av = (kk == 0) ? a0[p].x : (kk == 1) ? a0[p].y
                       : (kk == 2) ? a1[p].x : a1[p].y;
                acc[p][0] = fma2(av, w0, acc[p][0]);
                acc[p][1] = fma2(av, w1, acc[p][1]);
            }
        }
    }
}

__device__ __forceinline__ void mlp_rp(
    float tn,
    const float* __restrict__ W0, const float* __restrict__ b0,
    const float* __restrict__ W1, const float* __restrict__ b1,
    const float* __restrict__ Wo, const float* __restrict__ bo,
    const ull* __restrict__ aIn, ull* __restrict__ hS,
    ull out[RP][2], int lane)
{
    ull acc[RP][4];
    {   // bias + t * W0_row0 (same for both packed rows -> splat)
        float4 bv = ldg4(b0 + 4 * lane);
        float4 w0 = ldg4(W0 + 4 * lane);
        ull i0 = splat2(fmaf(tn, w0.x, bv.x));
        ull i1 = splat2(fmaf(tn, w0.y, bv.y));
        ull i2 = splat2(fmaf(tn, w0.z, bv.z));
        ull i3 = splat2(fmaf(tn, w0.w, bv.w));
#pragma unroll
        for (int p = 0; p < RP; p++) {
            acc[p][0] = i0; acc[p][1] = i1; acc[p][2] = i2; acc[p][3] = i3;
        }
    }
    gemm128_rp<HID>(W0 + MLPW, aIn, acc, lane);   // rows 1..64 of W0
#pragma unroll
    for (int p = 0; p < RP; p++) {
        ulonglong2 s0, s1;
        { float2 v = unpack2(acc[p][0]); s0.x = pack2(lipswish(v.x), lipswish(v.y)); }
        { float2 v = unpack2(acc[p][1]); s0.y = pack2(lipswish(v.x), lipswish(v.y)); }
        { float2 v = unpack2(acc[p][2]); s1.x = pack2(lipswish(v.x), lipswish(v.y)); }
        { float2 v = unpack2(acc[p][3]); s1.y = pack2(lipswish(v.x), lipswish(v.y)); }
        *reinterpret_cast<ulonglong2*>(hS + p * MLPW + 4 * lane)     = s0;
        *reinterpret_cast<ulonglong2*>(hS + p * MLPW + 4 * lane + 2) = s1;
    }
    __syncwarp();

    {
        float4 bv = ldg4(b1 + 4 * lane);
        ull i0 = splat2(bv.x), i1 = splat2(bv.y), i2 = splat2(bv.z), i3 = splat2(bv.w);
#pragma unroll
        for (int p = 0; p < RP; p++) {
            acc[p][0] = i0; acc[p][1] = i1; acc[p][2] = i2; acc[p][3] = i3;
        }
    }
    gemm128_rp<MLPW>(W1, hS, acc, lane);
    __syncwarp();   // all lanes done reading h1 before in-place overwrite
#pragma unroll
    for (int p = 0; p < RP; p++) {
        ulonglong2 s0, s1;
        { float2 v = unpack2(acc[p][0]); s0.x = pack2(lipswish(v.x), lipswish(v.y)); }
        { float2 v = unpack2(acc[p][1]); s0.y = pack2(lipswish(v.x), lipswish(v.y)); }
        { float2 v = unpack2(acc[p][2]); s1.x = pack2(lipswish(v.x), lipswish(v.y)); }
        { float2 v = unpack2(acc[p][3]); s1.y = pack2(lipswish(v.x), lipswish(v.y)); }
        *reinterpret_cast<ulonglong2*>(hS + p * MLPW + 4 * lane)     = s0;
        *reinterpret_cast<ulonglong2*>(hS + p * MLPW + 4 * lane + 2) = s1;
    }
    __syncwarp();

    ull acc2[RP][2];
    {
        float2 bv = ldg2f(bo + 2 * lane);
        ull i0 = splat2(bv.x), i1 = splat2(bv.y);
#pragma unroll
        for (int p = 0; p < RP; p++) { acc2[p][0] = i0; acc2[p][1] = i1; }
    }
    gemm64_rp<MLPW>(Wo, hS, acc2, lane);
#pragma unroll
    for (int p = 0; p < RP; p++) {
#pragma unroll
        for (int j = 0; j < 2; j++) {
            float2 v = unpack2(acc2[p][j]);
            out[p][j] = pack2(tanhf(v.x), tanhf(v.y));
        }
    }
}

// Drift warp only. Unpacks row-paired z into compact zc (reuses hD), then
// lane (r = lane>>3, d = lane&7) computes readout for 4 rows.
__device__ __forceinline__ void readout_rp(
    const ull z[RP][2], float* __restrict__ zc,
    const float (*sRWt)[68], const float* __restrict__ sRB,
    float* __restrict__ out, int rowbase, int tIdx, float tval, int lane)
{
#pragma unroll
    for (int p = 0; p < RP; p++) {
        float2 v0 = unpack2(z[p][0]);     // (row2p_c0, row2p+1_c0)
        float2 v1 = unpack2(z[p][1]);
        *reinterpret_cast<float2*>(zc + (2 * p) * HID + 2 * lane)     = make_float2(v0.x, v1.x);
        *reinterpret_cast<float2*>(zc + (2 * p + 1) * HID + 2 * lane) = make_float2(v0.y, v1.y);
    }
    __syncwarp();
    const int d = lane & 7;
    const int r = lane >> 3;
    float acc = sRB[d];
#pragma unroll
    for (int hb = 0; hb < HID / 4; hb++) {
        float4 zv = *reinterpret_cast<const float4*>(zc + r * HID + hb * 4);
        float4 wv = *reinterpret_cast<const float4*>(&sRWt[d][hb * 4]);
        acc = fmaf(zv.x, wv.x, acc);
        acc = fmaf(zv.y, wv.y, acc);
        acc = fmaf(zv.z, wv.z, acc);
        acc = fmaf(zv.w, wv.w, acc);
    }
    size_t base = ((size_t)(rowbase + r) * T_STEPS + tIdx) * (DOUT + 1);
    out[base + 1 + d] = acc;
    if (d == 0) out[base] = tval;
    __syncwarp();   // zc (hD) reads done before the MLP overwrites it
}

__global__ void __launch_bounds__(NWARPS * 32, 1)
sde_kernel(const float* __restrict__ ts,
           const float* __restrict__ dW,
           const float* __restrict__ dW0, const float* __restrict__ db0,
           const float* __restrict__ dW1, const float* __restrict__ db1,
           const float* __restrict__ dWo, const float* __restrict__ dbo,
           const float* __restrict__ fW0, const float* __restrict__ fb0,
           const float* __restrict__ fW1, const float* __restrict__ fb1,
           const float* __restrict__ fWo, const float* __restrict__ fbo,
           const float* __restrict__ RW, const float* __restrict__ rb,
           float* __restrict__ out)
{
    extern __shared__ char dyn[];
    QShm* Q = reinterpret_cast<QShm*>(dyn);
    float (*sRWt)[68] = reinterpret_cast<float(*)[68]>(dyn + QP * sizeof(QShm));
    float* sRB = reinterpret_cast<float*>(dyn + QP * sizeof(QShm) + DOUT * 68 * sizeof(float));

    const int tid  = threadIdx.x;
    const int w    = tid >> 5;
    const int lane = tid & 31;
    const int q    = w >> 1;
    const bool isDrift = (w & 1) == 0;
    const int role = isDrift ? 0 : 1;
    QShm& S = Q[q];
    ull* hS = isDrift ? &S.hD[0][0] : &S.hF[0][0];
    ull* myAIn  = &S.aIn[role][0][0];
    ull* myEx   = &S.ex[role][0][0];
    const ull* otherEx = &S.ex[role ^ 1][0][0];
    const int rowbase = (blockIdx.x * QP + q) * (2 * RP);

    for (int i = tid; i < HID * DOUT; i += blockDim.x)
        sRWt[i & 7][i >> 3] = __ldg(RW + i);        // RW is (64, 8) row-major
    if (tid < DOUT) sRB[tid] = __ldg(rb + tid);

    const float t0  = __ldg(ts + 0);
    const float dt  = __ldg(ts + 1) - t0;
    const float sdt = sqrtf(dt);
    const ull dt2   = splat2(dt);
    const ull hdt2  = splat2(0.5f * dt);
    const ull half2 = splat2(0.5f);
    const ull two2  = splat2(2.0f);
    const ull one2  = splat2(1.0f);
    const ull sdt2  = splat2(sdt);
    constexpr ull SGN2 = 0x8000000080000000ULL;

    const float* W0 = isDrift ? dW0 : fW0; const float* b0 = isDrift ? db0 : fb0;
    const float* W1 = isDrift ? dW1 : fW1; const float* b1 = isDrift ? db1 : fb1;
    const float* Wo = isDrift ? dWo : fWo; const float* bo = isDrift ? dbo : fbo;

    ull z[RP][2], zh[RP][2], ff[RP][2], gg[RP][2], res[RP][2];

    __syncthreads();   // sRWt visible block-wide (before any early exit)

    if (rowbase >= B_SZ) return;   // tail pairs (48 of 4144 row-slots) idle

    const unsigned dwRawAddr = smem_u32(&S.dwRaw[0][0][0]);   // 3 x 1024 B ring

    // ---- prologue: both warps hold full state, stage own aIn = ones ----
#pragma unroll
    for (int p = 0; p < RP; p++) {
        z[p][0] = z[p][1] = one2;
        zh[p][0] = zh[p][1] = one2;
        ulonglong2 o; o.x = one2; o.y = one2;
        *reinterpret_cast<ulonglong2*>(myAIn + p * HID + 2 * lane) = o;
    }
    if (!isDrift) {
        // cp.async raw dW (t=0) into ring slot 0: 4 rows x 256 B, contiguous
        const char* gsrc = (const char*)(dW + (size_t)rowbase * HID);
        CP_ASYNC16(dwRawAddr + lane * 16u,        gsrc + lane * 16);
        CP_ASYNC16(dwRawAddr + lane * 16u + 512u, gsrc + lane * 16 + 512);
        CP_COMMIT();
    }
    __syncwarp();

    // f0 (drift) / g0 (diff) at t = ts[0], x0 = ones
    mlp_rp(t0, W0, b0, W1, b1, Wo, bo, myAIn, hS, res, lane);
#pragma unroll
    for (int p = 0; p < RP; p++) {
        ulonglong2 v; v.x = res[p][0]; v.y = res[p][1];
        *reinterpret_cast<ulonglong2*>(myEx + p * HID + 2 * lane) = v;
    }
    if (!isDrift) CP_WAIT0();    // slot 0 landed (hidden under the mlp)
    pair_sync(q);                // exchange f0/g0 + publish dw slot 0

#pragma unroll
    for (int p = 0; p < RP; p++) {
        ulonglong2 v = *reinterpret_cast<const ulonglong2*>(otherEx + p * HID + 2 * lane);
        ff[p][0] = isDrift ? res[p][0] : v.x;
        ff[p][1] = isDrift ? res[p][1] : v.y;
        gg[p][0] = isDrift ? v.x : res[p][0];
        gg[p][1] = isDrift ? v.y : res[p][1];
    }
    if (isDrift)
        readout_rp(z, reinterpret_cast<float*>(&S.hD[0][0]), sRWt, sRB,
                   out, rowbase, 0, t0, lane);   // z = ones

    int sCur = 0;                // ring slot holding dw_n
    for (int n = 0; n < NSTEP; n++) {
        const float tn = __ldg(ts + n + 1);
        int sNxt = sCur + 1; if (sNxt == 3) sNxt = 0;

        if (!isDrift && n + 1 < NSTEP) {
            // fire-and-forget dw_{n+1} into ring slot sNxt (hidden under mlp)
            const char* gsrc = (const char*)(dW + ((size_t)(n + 1) * B_SZ + rowbase) * HID);
            unsigned dst = dwRawAddr + (unsigned)sNxt * 1024u + lane * 16u;
            CP_ASYNC16(dst,        gsrc + lane * 16);
            CP_ASYNC16(dst + 512u, gsrc + lane * 16 + 512);
            CP_COMMIT();
        }

        // ---- integration (BOTH warps, redundant): zhat_{n+1} ----
        {
            const float* raw = &S.dwRaw[sCur][0][0];
#pragma unroll
            for (int p = 0; p < RP; p++) {
                float2 a = *reinterpret_cast<const float2*>(raw + (2 * p) * HID + 2 * lane);
                float2 b = *reinterpret_cast<const float2*>(raw + (2 * p + 1) * HID + 2 * lane);
                ull dwp0 = mul2(pack2(a.x, b.x), sdt2);
                ull dwp1 = mul2(pack2(a.y, b.y), sdt2);
                ull t1;
                t1 = fma2(two2, z[p][0], zh[p][0] ^ SGN2);
                t1 = fma2(ff[p][0], dt2, t1);
                zh[p][0] = fma2(gg[p][0], dwp0, t1);
                t1 = fma2(two2, z[p][1], zh[p][1] ^ SGN2);
                t1 = fma2(ff[p][1], dt2, t1);
                zh[p][1] = fma2(gg[p][1], dwp1, t1);
                ulonglong2 o; o.x = zh[p][0]; o.y = zh[p][1];
                *reinterpret_cast<ulonglong2*>(myAIn + p * HID + 2 * lane) = o;
            }
        }
        __syncwarp();            // own aIn staged (intra-warp only)

        mlp_rp(tn, W0, b0, W1, b1, Wo, bo, myAIn, hS, res, lane);

#pragma unroll
        for (int p = 0; p < RP; p++) {
            ulonglong2 v; v.x = res[p][0]; v.y = res[p][1];
            *reinterpret_cast<ulonglong2*>(myEx + p * HID + 2 * lane) = v;
        }
        if (!isDrift) CP_WAIT0();    // dw_{n+1} landed
        pair_sync(q);                // THE single per-step barrier

        // ---- z update (BOTH warps, redundant) ----
        {
            const float* raw = &S.dwRaw[sCur][0][0];   // slot n untouched by sNxt fire
#pragma unroll
            for (int p = 0; p < RP; p++) {
                ulonglong2 v = *reinterpret_cast<const ulonglong2*>(otherEx + p * HID + 2 * lane);
                ull fn[2], gn[2];
                fn[0] = isDrift ? res[p][0] : v.x;
                fn[1] = isDrift ? res[p][1] : v.y;
                gn[0] = isDrift ? v.x : res[p][0];
                gn[1] = isDrift ? v.y : res[p][1];
                float2 a = *reinterpret_cast<const float2*>(raw + (2 * p) * HID + 2 * lane);
                float2 b = *reinterpret_cast<const float2*>(raw + (2 * p + 1) * HID + 2 * lane);
                ull dwp[2];
                dwp[0] = mul2(pack2(a.x, b.x), sdt2);
                dwp[1] = mul2(pack2(a.y, b.y), sdt2);
#pragma unroll
                for (int j = 0; j < 2; j++) {
                    ull s1 = add2(ff[p][j], fn[j]);
                    z[p][j] = fma2(s1, hdt2, z[p][j]);
                    ull s2 = mul2(add2(gg[p][j], gn[j]), half2);
                    z[p][j] = fma2(s2, dwp[j], z[p][j]);
                    ff[p][j] = fn[j];
                    gg[p][j] = gn[j];
                }
            }
        }

        if (isDrift) {
            // readout of z_{n+1} overlaps the diff warp's next-step progress
            readout_rp(z, reinterpret_cast<float*>(&S.hD[0][0]), sRWt, sRB,
                       out, rowbase, n + 1, tn, lane);
        }
        sCur = sNxt;
    }
}

extern "C" void kernel_launch(void* const* d_in, const int* in_sizes, int n_in,
                              void* d_out, int out_size) {
    (void)in_sizes; (void)n_in; (void)out_size;
    const float* ts  = (const float*)d_in[0];
    // d_in[1] = batch_size (int32 scalar) — shapes are fixed constants here
    const float* dW  = (const float*)d_in[2];
    const float* dW0 = (const float*)d_in[3];
    const float* db0 = (const float*)d_in[4];
    const float* dW1 = (const float*)d_in[5];
    const float* db1 = (const float*)d_in[6];
    const float* dWo = (const float*)d_in[7];
    const float* dbo = (const float*)d_in[8];
    const float* fW0 = (const float*)d_in[9];
    const float* fb0 = (const float*)d_in[10];
    const float* fW1 = (const float*)d_in[11];
    const float* fb1 = (const float*)d_in[12];
    const float* fWo = (const float*)d_in[13];
    const float* fbo = (const float*)d_in[14];
    const float* RW  = (const float*)d_in[15];
    const float* rb  = (const float*)d_in[16];
    float* out = (float*)d_out;

    const int smem = QP * (int)sizeof(QShm) + DOUT * 68 * (int)sizeof(float) + 64;
    cudaFuncSetAttribute(sde_kernel, cudaFuncAttributeMaxDynamicSharedMemorySize, smem);

    sde_kernel<<<NCTA, NWARPS * 32, smem>>>(ts, dW,
                                            dW0, db0, dW1, db1, dWo, dbo,
                                            fW0, fb0, fW1, fb1, fWo, fbo,
                                            RW, rb, out);
}